// round 9
// baseline (speedup 1.0000x reference)
#include <cuda_runtime.h>
#include <cuda_fp16.h>
#include <cstdint>

#define DIM      128
#define N_NODES  50000
#define N_EDGES  625000
#define TILE_M   64
#define NTILES   ((N_NODES + TILE_M - 1) / TILE_M)   // 782

// SMEM: fp16 tiles, row stride 272B (256B data + 16B pad -> ldmatrix
// conflict-free). A tiles are 64 rows; B tile is full 128 (weight) rows.
#define ASTRIDE   272
#define A_BYTES   (64 * ASTRIDE)                     // 17408
#define SM_AHI    0
#define SM_ALO    A_BYTES
#define SM_BHI    (2 * A_BYTES)
#define SM_TOTAL  (2 * A_BYTES + 128 * ASTRIDE)      // 69632 -> 2 CTAs/SM

// ---------------- scratch (device globals) ----------------------------------
__device__ float4 g_aggX[(size_t)N_NODES * (DIM / 4)];  // sum of X[dst] per src
__device__ float  g_deg[N_NODES];                       // degree per src
__device__ __half g_Wh[2][DIM * DIM];                   // fp16 weights [msg, lin]
__device__ int    g_ei_is_i64;

// ---------------- helpers ----------------------------------------------------
__device__ __forceinline__ uint32_t smem_u32(const void* p) {
    uint32_t a;
    asm("{ .reg .u64 t; cvta.to.shared.u64 t, %1; cvt.u32.u64 %0, t; }" : "=r"(a) : "l"(p));
    return a;
}

#define LDSM_X4(r, addr)                                                        \
    asm volatile("ldmatrix.sync.aligned.m8n8.x4.shared.b16 {%0,%1,%2,%3}, [%4];"\
                 : "=r"((r)[0]), "=r"((r)[1]), "=r"((r)[2]), "=r"((r)[3])       \
                 : "r"(addr))
#define MMA_FP16(c, a, b0, b1)                                                  \
    asm volatile("mma.sync.aligned.m16n8k16.row.col.f32.f16.f16.f32 "           \
                 "{%0,%1,%2,%3}, {%4,%5,%6,%7}, {%8,%9}, {%0,%1,%2,%3};"        \
                 : "+f"((c)[0]), "+f"((c)[1]), "+f"((c)[2]), "+f"((c)[3])       \
                 : "r"((a)[0]), "r"((a)[1]), "r"((a)[2]), "r"((a)[3]),          \
                   "r"(b0), "r"(b1))

// Split (a,b) -> fp16 hi pair + fp16 residual pair; store packed u32.
__device__ __forceinline__ void store_pair(char* hi_t, char* lo_t, int row, int col,
                                           float a, float b) {
    const uint32_t off = (uint32_t)row * ASTRIDE + (uint32_t)col * 2;
    __half2 h = __floats2half2_rn(a, b);
    float ra = a - __half2float(__low2half(h));
    float rb = b - __half2float(__high2half(h));
    __half2 l = __floats2half2_rn(ra, rb);
    *(uint32_t*)(hi_t + off) = *(uint32_t*)&h;
    *(uint32_t*)(lo_t + off) = *(uint32_t*)&l;
}

// ---------------- small kernels ---------------------------------------------
__global__ void detect_ei_kernel(const unsigned* __restrict__ p32) {
    __shared__ unsigned red[256];
    unsigned acc = 0;
    for (int i = threadIdx.x; i < 1024; i += 256) {
        acc |= p32[2 * i + 1];
        acc |= p32[2 * (N_EDGES / 2 + i) + 1];
    }
    red[threadIdx.x] = acc;
    __syncthreads();
    for (int s = 128; s > 0; s >>= 1) {
        if (threadIdx.x < s) red[threadIdx.x] |= red[threadIdx.x + s];
        __syncthreads();
    }
    if (threadIdx.x == 0) g_ei_is_i64 = (red[0] == 0) ? 1 : 0;
}

__global__ void prep_kernel(const float* __restrict__ msg_w,
                            const float* __restrict__ lin_w) {
    int i = blockIdx.x * blockDim.x + threadIdx.x;
    if (i < DIM * DIM) {
        g_Wh[0][i] = __float2half(msg_w[i]);
        g_Wh[1][i] = __float2half(lin_w[i]);
    }
}

__global__ void zero_kernel() {
    int i = blockIdx.x * blockDim.x + threadIdx.x;
    if (i < N_NODES * (DIM / 4)) g_aggX[i] = make_float4(0.f, 0.f, 0.f, 0.f);
    if (i < N_NODES) g_deg[i] = 0.f;
}

// scatter: aggX[src] += X[dst]; deg[src] += 1. One warp per 4 edges (MLP=4).
__global__ void scatter_kernel(const void* __restrict__ ei_raw,
                               const float* __restrict__ X) {
    const int e0 = (blockIdx.x * (blockDim.x >> 5) + (threadIdx.x >> 5)) * 4;
    if (e0 >= N_EDGES) return;
    const int lane = threadIdx.x & 31;
    const int n = (N_EDGES - e0 < 4) ? (N_EDGES - e0) : 4;

    unsigned s[4], d[4];
    bool ok[4];
    if (g_ei_is_i64) {
        const long long* p = (const long long*)ei_raw;
        #pragma unroll
        for (int i = 0; i < 4; i++) {
            s[i] = (i < n) ? (unsigned)__ldg(p + e0 + i) : 0u;
            d[i] = (i < n) ? (unsigned)__ldg(p + N_EDGES + e0 + i) : 0u;
        }
    } else {
        const int* p = (const int*)ei_raw;
        #pragma unroll
        for (int i = 0; i < 4; i++) {
            s[i] = (i < n) ? (unsigned)__ldg(p + e0 + i) : 0u;
            d[i] = (i < n) ? (unsigned)__ldg(p + N_EDGES + e0 + i) : 0u;
        }
    }
    #pragma unroll
    for (int i = 0; i < 4; i++)
        ok[i] = (i < n) && s[i] < N_NODES && d[i] < N_NODES;

    const float4* Xv = reinterpret_cast<const float4*>(X);
    float4 v[4];
    #pragma unroll
    for (int i = 0; i < 4; i++)
        v[i] = ok[i] ? __ldg(Xv + (size_t)d[i] * (DIM / 4) + lane)
                     : make_float4(0.f, 0.f, 0.f, 0.f);
    #pragma unroll
    for (int i = 0; i < 4; i++) {
        if (!ok[i]) continue;
        float4* a = &g_aggX[(size_t)s[i] * (DIM / 4) + lane];
        asm volatile("red.global.add.v4.f32 [%0], {%1, %2, %3, %4};"
                     :: "l"(a), "f"(v[i].x), "f"(v[i].y), "f"(v[i].z), "f"(v[i].w)
                     : "memory");
        if (lane == 0)
            asm volatile("red.global.add.f32 [%0], %1;"
                         :: "l"(&g_deg[s[i]]), "f"(1.0f) : "memory");
    }
}

// ---------------- fused double-GEMM (mma.sync fp16 hi/lo, 2 passes) ----------
// 256 threads = 8 warps. Warp w: row strip s=w>>1 (rows 16s..16s+15 of 64),
// column half h=w&1 (cols 64h..64h+63). acc[8][4] = 32 regs.
//   y   = msg_W . aggX[row] + deg[row]*msg_b + (1+eps)*X[row]
//   out = relu(lin_W . y + lin_b)

__device__ __forceinline__ void fill_B(char* smem, const __half* __restrict__ wsrc,
                                       int tid) {
    const int row = tid >> 1;                    // weight row g = output col n
    const int c0  = (tid & 1) * 64;
    const uint4* src = (const uint4*)(wsrc + (size_t)row * DIM + c0);  // 8 x 16B
    uint4* dst = (uint4*)(smem + SM_BHI + (uint32_t)row * ASTRIDE + (uint32_t)c0 * 2);
    #pragma unroll
    for (int i = 0; i < 8; i++) dst[i] = __ldg(src + i);
}

__device__ __forceinline__ void do_gemm(uint32_t sb, int s, int h, int t,
                                        float (*acc)[4]) {
    #pragma unroll 1
    for (int k = 0; k < 8; k++) {
        const uint32_t a_addr = sb + SM_AHI + (uint32_t)(s * 16 + (t & 15)) * ASTRIDE
                              + (uint32_t)k * 32 + (uint32_t)(t >> 4) * 16;
        uint32_t ah[4], al[4];
        LDSM_X4(ah, a_addr);
        LDSM_X4(al, a_addr + A_BYTES);
        #pragma unroll
        for (int jp = 0; jp < 4; jp++) {
            const uint32_t b_addr = sb + SM_BHI
                + (uint32_t)((h * 8 + jp * 2) * 8 + (t >> 4) * 8 + (t & 7)) * ASTRIDE
                + (uint32_t)k * 32 + (uint32_t)((t >> 3) & 1) * 16;
            uint32_t bb[4];
            LDSM_X4(bb, b_addr);
            MMA_FP16(acc[jp * 2 + 0], ah, bb[0], bb[1]);
            MMA_FP16(acc[jp * 2 + 0], al, bb[0], bb[1]);
            MMA_FP16(acc[jp * 2 + 1], ah, bb[2], bb[3]);
            MMA_FP16(acc[jp * 2 + 1], al, bb[2], bb[3]);
        }
    }
}

__global__ void __launch_bounds__(256, 2)
fused_kernel(const float* __restrict__ X,
             const float* __restrict__ msg_b, const float* __restrict__ lin_b,
             const float* __restrict__ eps_ptr, float* __restrict__ out) {
    extern __shared__ char smem[];
    const uint32_t sb = smem_u32(smem);
    const int tid = threadIdx.x;
    const int w = tid >> 5, t = tid & 31;
    const int s = w >> 1, h = w & 1;
    const int g = t >> 2, tig = t & 3;
    const int base = blockIdx.x * TILE_M;

    // ---- fill A (aggX hi/lo split) and B (msg_w fp16) ----
    {
        const int row = tid >> 2;                 // 0..63
        const int c0 = (tid & 3) * 32;
        const int grow = base + row;
        const bool v = (grow < N_NODES);
        const float4* ar = (const float4*)((const float*)g_aggX + (size_t)grow * DIM + c0);
        #pragma unroll
        for (int c = 0; c < 32; c += 4) {
            float4 a = v ? __ldg(ar + c / 4) : make_float4(0.f, 0.f, 0.f, 0.f);
            store_pair(smem + SM_AHI, smem + SM_ALO, row, c0 + c, a.x, a.y);
            store_pair(smem + SM_AHI, smem + SM_ALO, row, c0 + c + 2, a.z, a.w);
        }
        fill_B(smem, g_Wh[0], tid);
    }
    __syncthreads();

    float acc[8][4];
    #pragma unroll
    for (int j = 0; j < 8; j++)
        #pragma unroll
        for (int i = 0; i < 4; i++) acc[j][i] = 0.f;

    // ---- GEMM 1: acc = msg_W . aggX ----
    do_gemm(sb, s, h, t, acc);
    __syncthreads();   // all reads of A (warp pair) and B (all warps) done

    // ---- epilogue 1: y = acc + deg*msg_b + (1+eps)X -> back into A tiles ----
    const float epsv = 1.0f + __ldg(eps_ptr);
    const int r0 = s * 16 + g, r1 = r0 + 8;
    const int gr0 = base + r0, gr1 = base + r1;
    const bool v0 = (gr0 < N_NODES), v1 = (gr1 < N_NODES);
    const float d0 = v0 ? __ldg(&g_deg[gr0]) : 0.f;
    const float d1 = v1 ? __ldg(&g_deg[gr1]) : 0.f;
    #pragma unroll
    for (int j = 0; j < 8; j++) {
        const int col = h * 64 + j * 8 + 2 * tig;
        float2 mb = __ldg((const float2*)(msg_b + col));
        float2 x0 = v0 ? __ldg((const float2*)(X + (size_t)gr0 * DIM + col)) : make_float2(0.f, 0.f);
        float2 x1 = v1 ? __ldg((const float2*)(X + (size_t)gr1 * DIM + col)) : make_float2(0.f, 0.f);
        float y00 = acc[j][0] + d0 * mb.x + epsv * x0.x;
        float y01 = acc[j][1] + d0 * mb.y + epsv * x0.y;
        float y10 = acc[j][2] + d1 * mb.x + epsv * x1.x;
        float y11 = acc[j][3] + d1 * mb.y + epsv * x1.y;
        store_pair(smem + SM_AHI, smem + SM_ALO, r0, col, y00, y01);
        store_pair(smem + SM_AHI, smem + SM_ALO, r1, col, y10, y11);
        acc[j][0] = acc[j][1] = acc[j][2] = acc[j][3] = 0.f;
    }
    fill_B(smem, g_Wh[1], tid);   // B(msg) reads all completed at last sync
    __syncthreads();

    // ---- GEMM 2: acc = lin_W . y ----
    do_gemm(sb, s, h, t, acc);

    // ---- epilogue 2: out = relu(acc + lin_b) ----
    #pragma unroll
    for (int j = 0; j < 8; j++) {
        const int col = h * 64 + j * 8 + 2 * tig;
        float2 lb = __ldg((const float2*)(lin_b + col));
        if (v0) {
            float2 o;
            o.x = fmaxf(acc[j][0] + lb.x, 0.f);
            o.y = fmaxf(acc[j][1] + lb.y, 0.f);
            *(float2*)(out + (size_t)gr0 * DIM + col) = o;
        }
        if (v1) {
            float2 o;
            o.x = fmaxf(acc[j][2] + lb.x, 0.f);
            o.y = fmaxf(acc[j][3] + lb.y, 0.f);
            *(float2*)(out + (size_t)gr1 * DIM + col) = o;
        }
    }
}

// ---------------- launch ----------------------------------------------------
extern "C" void kernel_launch(void* const* d_in, const int* in_sizes, int n_in,
                              void* d_out, int out_size) {
    const float* X   = nullptr;
    const void*  ei  = nullptr;
    const float* eps = nullptr;
    const float* w[2] = {nullptr, nullptr};   // [msg_w, lin_w]
    const float* b[2] = {nullptr, nullptr};   // [msg_b, lin_b]
    int wi = 0, bi = 0;
    for (int i = 0; i < n_in; i++) {
        const int s = in_sizes[i];
        if      (s == N_NODES * DIM) X   = (const float*)d_in[i];
        else if (s == 2 * N_EDGES)   ei  = d_in[i];
        else if (s == 1)             eps = (const float*)d_in[i];
        else if (s == DIM * DIM)   { if (wi < 2) w[wi++] = (const float*)d_in[i]; }
        else if (s == DIM)         { if (bi < 2) b[bi++] = (const float*)d_in[i]; }
    }
    float* out = (float*)d_out;

    cudaFuncSetAttribute(fused_kernel, cudaFuncAttributeMaxDynamicSharedMemorySize, SM_TOTAL);

    const int zero_blocks = (N_NODES * (DIM / 4) + 255) / 256;   // 6250
    const int scat_blocks = (N_EDGES + 31) / 32;                 // 4 edges/warp, 8 warps

    detect_ei_kernel<<<1, 256>>>((const unsigned*)ei);
    prep_kernel<<<(DIM * DIM + 255) / 256, 256>>>(w[0], w[1]);
    zero_kernel<<<zero_blocks, 256>>>();
    scatter_kernel<<<scat_blocks, 256>>>(ei, X);
    fused_kernel<<<NTILES, 256, SM_TOTAL>>>(X, b[0], b[1], eps, out);
}

// round 10
// speedup vs baseline: 1.2742x; 1.2742x over previous
#include <cuda_runtime.h>
#include <cuda_fp16.h>
#include <cstdint>

#define DIM      128
#define N_NODES  50000
#define N_EDGES  625000
#define TILE_M   128
#define NTILES   ((N_NODES + TILE_M - 1) / TILE_M)   // 391

// SMEM: fp16 128x128 tiles, row stride 272B (256B data + 16B pad -> ldmatrix
// conflict-free). Six tiles: X hi/lo, aggX hi/lo, lin_W, C.
#define ASTRIDE   272
#define TB        (128 * ASTRIDE)                    // 34816
#define SM_A1H    0
#define SM_A1L    (1 * TB)
#define SM_A2H    (2 * TB)
#define SM_A2L    (3 * TB)
#define SM_B1     (4 * TB)
#define SM_B2     (5 * TB)
#define SM_TOTAL  (6 * TB)                           // 208896 B (fits 227KB)

// ---------------- scratch (device globals) ----------------------------------
__device__ float4 g_aggX[(size_t)N_NODES * (DIM / 4)];  // sum of X[dst] per src
__device__ float  g_deg[N_NODES];                       // degree per src
__device__ __half g_Wh[2][DIM * DIM];                   // fp16: [lin_W, C=lin_W.msg_W]
__device__ float  g_c2[DIM];                            // lin_W . msg_b
__device__ int    g_ei_is_i64;

// ---------------- helpers ----------------------------------------------------
__device__ __forceinline__ uint32_t smem_u32(const void* p) {
    uint32_t a;
    asm("{ .reg .u64 t; cvta.to.shared.u64 t, %1; cvt.u32.u64 %0, t; }" : "=r"(a) : "l"(p));
    return a;
}

#define LDSM_X4(r, addr)                                                        \
    asm volatile("ldmatrix.sync.aligned.m8n8.x4.shared.b16 {%0,%1,%2,%3}, [%4];"\
                 : "=r"((r)[0]), "=r"((r)[1]), "=r"((r)[2]), "=r"((r)[3])       \
                 : "r"(addr))
#define MMA_FP16(c, a, b0, b1)                                                  \
    asm volatile("mma.sync.aligned.m16n8k16.row.col.f32.f16.f16.f32 "           \
                 "{%0,%1,%2,%3}, {%4,%5,%6,%7}, {%8,%9}, {%0,%1,%2,%3};"        \
                 : "+f"((c)[0]), "+f"((c)[1]), "+f"((c)[2]), "+f"((c)[3])       \
                 : "r"((a)[0]), "r"((a)[1]), "r"((a)[2]), "r"((a)[3]),          \
                   "r"(b0), "r"(b1))

// Split (a,b) -> fp16 hi pair + fp16 residual pair; store packed u32.
__device__ __forceinline__ void store_pair(char* hi_t, char* lo_t, int row, int col,
                                           float a, float b) {
    const uint32_t off = (uint32_t)row * ASTRIDE + (uint32_t)col * 2;
    __half2 h = __floats2half2_rn(a, b);
    float ra = a - __half2float(__low2half(h));
    float rb = b - __half2float(__high2half(h));
    __half2 l = __floats2half2_rn(ra, rb);
    *(uint32_t*)(hi_t + off) = *(uint32_t*)&h;
    *(uint32_t*)(lo_t + off) = *(uint32_t*)&l;
}

// ---------------- small kernels ---------------------------------------------
__global__ void detect_ei_kernel(const unsigned* __restrict__ p32) {
    __shared__ unsigned red[256];
    unsigned acc = 0;
    for (int i = threadIdx.x; i < 1024; i += 256) {
        acc |= p32[2 * i + 1];
        acc |= p32[2 * (N_EDGES / 2 + i) + 1];
    }
    red[threadIdx.x] = acc;
    __syncthreads();
    for (int s = 128; s > 0; s >>= 1) {
        if (threadIdx.x < s) red[threadIdx.x] |= red[threadIdx.x + s];
        __syncthreads();
    }
    if (threadIdx.x == 0) g_ei_is_i64 = (red[0] == 0) ? 1 : 0;
}

// lin_W -> fp16 (B1 source)
__global__ void prep_w_kernel(const float* __restrict__ lin_w) {
    int i = blockIdx.x * blockDim.x + threadIdx.x;
    if (i < DIM * DIM) g_Wh[0][i] = __float2half(lin_w[i]);
}

// C[i][j] = sum_k lin_W[i][k]*msg_W[k][j] (fp32 accumulate, fp16 store)
// and c2[i] = sum_k lin_W[i][k]*msg_b[k]. One CTA per output row i.
__global__ void prep_c_kernel(const float* __restrict__ lin_w,
                              const float* __restrict__ msg_w,
                              const float* __restrict__ msg_b) {
    __shared__ float s[DIM];
    __shared__ float red[DIM];
    const int i = blockIdx.x, j = threadIdx.x;
    s[j] = lin_w[(size_t)i * DIM + j];
    __syncthreads();
    float acc = 0.f;
    #pragma unroll 8
    for (int k = 0; k < DIM; k++)
        acc += s[k] * __ldg(msg_w + (size_t)k * DIM + j);   // coalesced over j
    g_Wh[1][(size_t)i * DIM + j] = __float2half(acc);
    // c2 reduction
    red[j] = s[j] * __ldg(msg_b + j);
    __syncthreads();
    for (int st = 64; st > 0; st >>= 1) {
        if (j < st) red[j] += red[j + st];
        __syncthreads();
    }
    if (j == 0) g_c2[i] = red[0];
}

__global__ void zero_kernel() {
    int i = blockIdx.x * blockDim.x + threadIdx.x;
    if (i < N_NODES * (DIM / 4)) g_aggX[i] = make_float4(0.f, 0.f, 0.f, 0.f);
    if (i < N_NODES) g_deg[i] = 0.f;
}

// scatter: aggX[src] += X[dst]; deg[src] += 1. One warp per edge (proven best).
__global__ void scatter_kernel(const void* __restrict__ ei_raw,
                               const float* __restrict__ X) {
    const int e = blockIdx.x * (blockDim.x >> 5) + (threadIdx.x >> 5);
    if (e >= N_EDGES) return;
    const int lane = threadIdx.x & 31;

    unsigned src, dst;
    if (g_ei_is_i64) {
        const long long* p = (const long long*)ei_raw;
        src = (unsigned)p[e];
        dst = (unsigned)p[N_EDGES + e];
    } else {
        const int* p = (const int*)ei_raw;
        src = (unsigned)p[e];
        dst = (unsigned)p[N_EDGES + e];
    }
    if (src >= N_NODES || dst >= N_NODES) return;

    const float4 v = __ldg(reinterpret_cast<const float4*>(X) + (size_t)dst * (DIM / 4) + lane);
    float4* a = &g_aggX[(size_t)src * (DIM / 4) + lane];
    asm volatile("red.global.add.v4.f32 [%0], {%1, %2, %3, %4};"
                 :: "l"(a), "f"(v.x), "f"(v.y), "f"(v.z), "f"(v.w) : "memory");
    if (lane == 0)
        asm volatile("red.global.add.f32 [%0], %1;" :: "l"(&g_deg[src]), "f"(1.0f) : "memory");
}

// ---------------- final kernel: two independent GEMMs, one accumulator ------
// out[n] = relu( (1+eps)X[n].lin_W^T + aggX[n].C^T + deg[n]*c2 + lin_b )
// 512 threads = 16 warps. Warp w: rows 16(w>>1)..+15, col half (w&1)*64.
// A1 = (1+eps)X (hi/lo), A2 = aggX (hi/lo), B1 = lin_W fp16, B2 = C fp16.
__global__ void __launch_bounds__(512, 1)
final_kernel(const float* __restrict__ X,
             const float* __restrict__ lin_b,
             const float* __restrict__ eps_ptr, float* __restrict__ out) {
    extern __shared__ char smem[];
    const uint32_t sb = smem_u32(smem);
    const int tid = threadIdx.x;
    const int w = tid >> 5, t = tid & 31;
    const int s = w >> 1, h = w & 1;
    const int g = t >> 2, tig = t & 3;
    const int base = blockIdx.x * TILE_M;
    const float epsv = 1.0f + __ldg(eps_ptr);

    // ---- single fill phase: A1, A2 (split), B1, B2 (copy). Max MLP. ----
    {
        const int row = tid >> 2;                 // 0..127
        const int c0 = (tid & 3) * 32;
        const int grow = base + row;
        const bool v = (grow < N_NODES);
        const float4* xr = (const float4*)(X + (size_t)grow * DIM + c0);
        const float4* ar = (const float4*)((const float*)g_aggX + (size_t)grow * DIM + c0);
        #pragma unroll
        for (int c = 0; c < 32; c += 4) {
            float4 xv = v ? __ldg(xr + c / 4) : make_float4(0.f, 0.f, 0.f, 0.f);
            float4 av = v ? __ldg(ar + c / 4) : make_float4(0.f, 0.f, 0.f, 0.f);
            store_pair(smem + SM_A1H, smem + SM_A1L, row, c0 + c,
                       epsv * xv.x, epsv * xv.y);
            store_pair(smem + SM_A1H, smem + SM_A1L, row, c0 + c + 2,
                       epsv * xv.z, epsv * xv.w);
            store_pair(smem + SM_A2H, smem + SM_A2L, row, c0 + c, av.x, av.y);
            store_pair(smem + SM_A2H, smem + SM_A2L, row, c0 + c + 2, av.z, av.w);
        }
        // B copies: 2 x uint4 per tile per thread
        const uint4* b1s = (const uint4*)(&g_Wh[0][(size_t)row * DIM + c0]);
        const uint4* b2s = (const uint4*)(&g_Wh[1][(size_t)row * DIM + c0]);
        uint4* b1d = (uint4*)(smem + SM_B1 + (uint32_t)row * ASTRIDE + (uint32_t)c0 * 2);
        uint4* b2d = (uint4*)(smem + SM_B2 + (uint32_t)row * ASTRIDE + (uint32_t)c0 * 2);
        #pragma unroll
        for (int i = 0; i < 4; i++) { b1d[i] = __ldg(b1s + i); b2d[i] = __ldg(b2s + i); }
    }
    __syncthreads();

    float acc[8][4];
    #pragma unroll
    for (int j = 0; j < 8; j++)
        #pragma unroll
        for (int i = 0; i < 4; i++) acc[j][i] = 0.f;

    // ---- merged MMA region: acc = A1.B1 (2-pass) + A2.B2 (2-pass) ----
    #pragma unroll 1
    for (int k = 0; k < 8; k++) {
        const uint32_t a_off = (uint32_t)(s * 16 + (t & 15)) * ASTRIDE
                             + (uint32_t)k * 32 + (uint32_t)(t >> 4) * 16;
        uint32_t a1h[4], a1l[4], a2h[4], a2l[4];
        LDSM_X4(a1h, sb + SM_A1H + a_off);
        LDSM_X4(a1l, sb + SM_A1L + a_off);
        LDSM_X4(a2h, sb + SM_A2H + a_off);
        LDSM_X4(a2l, sb + SM_A2L + a_off);
        #pragma unroll
        for (int jp = 0; jp < 4; jp++) {
            const uint32_t b_off =
                  (uint32_t)((h * 8 + jp * 2) * 8 + (t >> 4) * 8 + (t & 7)) * ASTRIDE
                + (uint32_t)k * 32 + (uint32_t)((t >> 3) & 1) * 16;
            uint32_t b1[4], b2[4];
            LDSM_X4(b1, sb + SM_B1 + b_off);
            LDSM_X4(b2, sb + SM_B2 + b_off);
            MMA_FP16(acc[jp * 2 + 0], a1h, b1[0], b1[1]);
            MMA_FP16(acc[jp * 2 + 0], a1l, b1[0], b1[1]);
            MMA_FP16(acc[jp * 2 + 0], a2h, b2[0], b2[1]);
            MMA_FP16(acc[jp * 2 + 0], a2l, b2[0], b2[1]);
            MMA_FP16(acc[jp * 2 + 1], a1h, b1[2], b1[3]);
            MMA_FP16(acc[jp * 2 + 1], a1l, b1[2], b1[3]);
            MMA_FP16(acc[jp * 2 + 1], a2h, b2[2], b2[3]);
            MMA_FP16(acc[jp * 2 + 1], a2l, b2[2], b2[3]);
        }
    }

    // ---- epilogue: out = relu(acc + deg*c2 + lin_b) ----
    const int r0 = s * 16 + g, r1 = r0 + 8;
    const int gr0 = base + r0, gr1 = base + r1;
    const bool v0 = (gr0 < N_NODES), v1 = (gr1 < N_NODES);
    const float d0 = v0 ? __ldg(&g_deg[gr0]) : 0.f;
    const float d1 = v1 ? __ldg(&g_deg[gr1]) : 0.f;
    #pragma unroll
    for (int j = 0; j < 8; j++) {
        const int col = h * 64 + j * 8 + 2 * tig;
        float2 lb = __ldg((const float2*)(lin_b + col));
        float2 c2 = __ldg((const float2*)(g_c2 + col));
        if (v0) {
            float2 o;
            o.x = fmaxf(acc[j][0] + d0 * c2.x + lb.x, 0.f);
            o.y = fmaxf(acc[j][1] + d0 * c2.y + lb.y, 0.f);
            *(float2*)(out + (size_t)gr0 * DIM + col) = o;
        }
        if (v1) {
            float2 o;
            o.x = fmaxf(acc[j][2] + d1 * c2.x + lb.x, 0.f);
            o.y = fmaxf(acc[j][3] + d1 * c2.y + lb.y, 0.f);
            *(float2*)(out + (size_t)gr1 * DIM + col) = o;
        }
    }
}

// ---------------- launch ----------------------------------------------------
extern "C" void kernel_launch(void* const* d_in, const int* in_sizes, int n_in,
                              void* d_out, int out_size) {
    const float* X   = nullptr;
    const void*  ei  = nullptr;
    const float* eps = nullptr;
    const float* w[2] = {nullptr, nullptr};   // [msg_w, lin_w]
    const float* b[2] = {nullptr, nullptr};   // [msg_b, lin_b]
    int wi = 0, bi = 0;
    for (int i = 0; i < n_in; i++) {
        const int s = in_sizes[i];
        if      (s == N_NODES * DIM) X   = (const float*)d_in[i];
        else if (s == 2 * N_EDGES)   ei  = d_in[i];
        else if (s == 1)             eps = (const float*)d_in[i];
        else if (s == DIM * DIM)   { if (wi < 2) w[wi++] = (const float*)d_in[i]; }
        else if (s == DIM)         { if (bi < 2) b[bi++] = (const float*)d_in[i]; }
    }
    float* out = (float*)d_out;

    cudaFuncSetAttribute(final_kernel, cudaFuncAttributeMaxDynamicSharedMemorySize, SM_TOTAL);

    const int zero_blocks = (N_NODES * (DIM / 4) + 255) / 256;   // 6250
    const int scat_blocks = (N_EDGES + 7) / 8;                   // 78125

    detect_ei_kernel<<<1, 256>>>((const unsigned*)ei);
    prep_w_kernel<<<(DIM * DIM + 255) / 256, 256>>>(w[1]);
    prep_c_kernel<<<DIM, DIM>>>(w[1], w[0], b[0]);
    zero_kernel<<<zero_blocks, 256>>>();
    scatter_kernel<<<scat_blocks, 256>>>(ei, X);
    final_kernel<<<NTILES, 512, SM_TOTAL>>>(X, b[1], eps, out);
}

// round 11
// speedup vs baseline: 1.5728x; 1.2344x over previous
#include <cuda_runtime.h>
#include <cuda_fp16.h>
#include <cstdint>

#define DIM      128
#define N_NODES  50000
#define N_EDGES  625000
#define TILE_M   128
#define NTILES   ((N_NODES + TILE_M - 1) / TILE_M)   // 391

#define SCAN_BS  512
#define NBLK     ((N_NODES + SCAN_BS - 1) / SCAN_BS) // 98

// SMEM geometry for final kernel (unchanged from round 10)
#define ASTRIDE   272
#define TB        (128 * ASTRIDE)
#define SM_A1H    0
#define SM_A1L    (1 * TB)
#define SM_A2H    (2 * TB)
#define SM_A2L    (3 * TB)
#define SM_B1     (4 * TB)
#define SM_B2     (5 * TB)
#define SM_TOTAL  (6 * TB)                           // 208896 B

// ---------------- scratch (device globals) ----------------------------------
__device__ float4 g_aggX[(size_t)N_NODES * (DIM / 4)];
__device__ float  g_deg[N_NODES];
__device__ __half g_Wh[2][DIM * DIM];                // [lin_W, C=lin_W.msg_W]
__device__ float  g_c2[DIM];                         // lin_W . msg_b
__device__ int    g_ei_is_i64;
// CSR build
__device__ int    g_cnt[N_NODES];
__device__ int    g_off[N_NODES + 1];
__device__ int    g_cur[N_NODES];
__device__ int    g_bsum[NBLK];
__device__ int    g_sorted[N_EDGES];

// ---------------- helpers ----------------------------------------------------
__device__ __forceinline__ uint32_t smem_u32(const void* p) {
    uint32_t a;
    asm("{ .reg .u64 t; cvta.to.shared.u64 t, %1; cvt.u32.u64 %0, t; }" : "=r"(a) : "l"(p));
    return a;
}

#define LDSM_X4(r, addr)                                                        \
    asm volatile("ldmatrix.sync.aligned.m8n8.x4.shared.b16 {%0,%1,%2,%3}, [%4];"\
                 : "=r"((r)[0]), "=r"((r)[1]), "=r"((r)[2]), "=r"((r)[3])       \
                 : "r"(addr))
#define MMA_FP16(c, a, b0, b1)                                                  \
    asm volatile("mma.sync.aligned.m16n8k16.row.col.f32.f16.f16.f32 "           \
                 "{%0,%1,%2,%3}, {%4,%5,%6,%7}, {%8,%9}, {%0,%1,%2,%3};"        \
                 : "+f"((c)[0]), "+f"((c)[1]), "+f"((c)[2]), "+f"((c)[3])       \
                 : "r"((a)[0]), "r"((a)[1]), "r"((a)[2]), "r"((a)[3]),          \
                   "r"(b0), "r"(b1))

__device__ __forceinline__ void store_pair(char* hi_t, char* lo_t, int row, int col,
                                           float a, float b) {
    const uint32_t off = (uint32_t)row * ASTRIDE + (uint32_t)col * 2;
    __half2 h = __floats2half2_rn(a, b);
    float ra = a - __half2float(__low2half(h));
    float rb = b - __half2float(__high2half(h));
    __half2 l = __floats2half2_rn(ra, rb);
    *(uint32_t*)(hi_t + off) = *(uint32_t*)&h;
    *(uint32_t*)(lo_t + off) = *(uint32_t*)&l;
}

// dtype-adaptive edge decode
__device__ __forceinline__ void edge_decode(const void* ei, int e,
                                            unsigned& src, unsigned& dst) {
    if (g_ei_is_i64) {
        const long long* p = (const long long*)ei;
        src = (unsigned)__ldg(p + e);
        dst = (unsigned)__ldg(p + N_EDGES + e);
    } else {
        const int* p = (const int*)ei;
        src = (unsigned)__ldg(p + e);
        dst = (unsigned)__ldg(p + N_EDGES + e);
    }
}

// ---------------- prep kernels -----------------------------------------------
__global__ void detect_ei_kernel(const unsigned* __restrict__ p32) {
    __shared__ unsigned red[256];
    unsigned acc = 0;
    for (int i = threadIdx.x; i < 1024; i += 256) {
        acc |= p32[2 * i + 1];
        acc |= p32[2 * (N_EDGES / 2 + i) + 1];
    }
    red[threadIdx.x] = acc;
    __syncthreads();
    for (int s = 128; s > 0; s >>= 1) {
        if (threadIdx.x < s) red[threadIdx.x] |= red[threadIdx.x + s];
        __syncthreads();
    }
    if (threadIdx.x == 0) g_ei_is_i64 = (red[0] == 0) ? 1 : 0;
}

__global__ void prep_w_kernel(const float* __restrict__ lin_w) {
    int i = blockIdx.x * blockDim.x + threadIdx.x;
    if (i < DIM * DIM) g_Wh[0][i] = __float2half(lin_w[i]);
}

// C = lin_W . msg_W (fp32 acc, fp16 store); c2 = lin_W . msg_b
__global__ void prep_c_kernel(const float* __restrict__ lin_w,
                              const float* __restrict__ msg_w,
                              const float* __restrict__ msg_b) {
    __shared__ float s[DIM];
    __shared__ float red[DIM];
    const int i = blockIdx.x, j = threadIdx.x;
    s[j] = lin_w[(size_t)i * DIM + j];
    __syncthreads();
    float acc = 0.f;
    #pragma unroll 8
    for (int k = 0; k < DIM; k++)
        acc += s[k] * __ldg(msg_w + (size_t)k * DIM + j);
    g_Wh[1][(size_t)i * DIM + j] = __float2half(acc);
    red[j] = s[j] * __ldg(msg_b + j);
    __syncthreads();
    for (int st = 64; st > 0; st >>= 1) {
        if (j < st) red[j] += red[j + st];
        __syncthreads();
    }
    if (j == 0) g_c2[i] = red[0];
}

// ---------------- CSR build: zero counters, histogram, scan, reorder --------
__global__ void zero_cnt_kernel() {
    int i = blockIdx.x * blockDim.x + threadIdx.x;
    if (i < N_NODES) g_cnt[i] = 0;
}

__global__ void hist_kernel(const void* __restrict__ ei) {
    int e = blockIdx.x * blockDim.x + threadIdx.x;
    if (e >= N_EDGES) return;
    unsigned src, dst;
    edge_decode(ei, e, src, dst);
    if (src >= N_NODES || dst >= N_NODES) return;
    atomicAdd(&g_cnt[src], 1);
}

__global__ void scanA_kernel() {
    __shared__ int sm[SCAN_BS];
    const int t = threadIdx.x, b = blockIdx.x;
    const int i = b * SCAN_BS + t;
    const int v = (i < N_NODES) ? g_cnt[i] : 0;
    sm[t] = v;
    __syncthreads();
    for (int off = 1; off < SCAN_BS; off <<= 1) {
        int x = (t >= off) ? sm[t - off] : 0;
        __syncthreads();
        sm[t] += x;
        __syncthreads();
    }
    if (i < N_NODES) g_off[i] = sm[t] - v;          // exclusive, local
    if (t == SCAN_BS - 1) g_bsum[b] = sm[t];
}

__global__ void scanB_kernel() {
    if (threadIdx.x == 0) {
        int acc = 0;
        for (int b = 0; b < NBLK; b++) {
            int v = g_bsum[b];
            g_bsum[b] = acc;
            acc += v;
        }
        g_off[N_NODES] = acc;                        // total valid edges
    }
}

__global__ void scanC_kernel() {
    const int i = blockIdx.x * blockDim.x + threadIdx.x;
    if (i >= N_NODES) return;
    const int o = g_off[i] + g_bsum[i / SCAN_BS];
    g_off[i] = o;
    g_cur[i] = o;
    g_deg[i] = (float)g_cnt[i];
}

__global__ void reorder_kernel(const void* __restrict__ ei) {
    int e = blockIdx.x * blockDim.x + threadIdx.x;
    if (e >= N_EDGES) return;
    unsigned src, dst;
    edge_decode(ei, e, src, dst);
    if (src >= N_NODES || dst >= N_NODES) return;
    int pos = atomicAdd(&g_cur[src], 1);
    g_sorted[pos] = (int)dst;
}

// ---------------- SpMM: aggX[n] = sum over sorted dst rows of X --------------
// One warp per node; lane = one float4 column. 4 accumulators -> gather MLP=4.
__global__ void spmm_kernel(const float* __restrict__ X) {
    const int node = blockIdx.x * (blockDim.x >> 5) + (threadIdx.x >> 5);
    if (node >= N_NODES) return;
    const int lane = threadIdx.x & 31;
    const int start = __ldg(&g_off[node]);
    const int end   = __ldg(&g_off[node + 1]);
    const float4* Xv = (const float4*)X;

    float4 a0 = make_float4(0.f, 0.f, 0.f, 0.f);
    float4 a1 = a0, a2 = a0, a3 = a0;
    int i = start;
    for (; i + 4 <= end; i += 4) {
        const int d0 = __ldg(&g_sorted[i + 0]);
        const int d1 = __ldg(&g_sorted[i + 1]);
        const int d2 = __ldg(&g_sorted[i + 2]);
        const int d3 = __ldg(&g_sorted[i + 3]);
        float4 v0 = __ldg(Xv + (size_t)d0 * (DIM / 4) + lane);
        float4 v1 = __ldg(Xv + (size_t)d1 * (DIM / 4) + lane);
        float4 v2 = __ldg(Xv + (size_t)d2 * (DIM / 4) + lane);
        float4 v3 = __ldg(Xv + (size_t)d3 * (DIM / 4) + lane);
        a0.x += v0.x; a0.y += v0.y; a0.z += v0.z; a0.w += v0.w;
        a1.x += v1.x; a1.y += v1.y; a1.z += v1.z; a1.w += v1.w;
        a2.x += v2.x; a2.y += v2.y; a2.z += v2.z; a2.w += v2.w;
        a3.x += v3.x; a3.y += v3.y; a3.z += v3.z; a3.w += v3.w;
    }
    for (; i < end; i++) {
        const int d = __ldg(&g_sorted[i]);
        float4 v = __ldg(Xv + (size_t)d * (DIM / 4) + lane);
        a0.x += v.x; a0.y += v.y; a0.z += v.z; a0.w += v.w;
    }
    a0.x += a1.x + a2.x + a3.x;
    a0.y += a1.y + a2.y + a3.y;
    a0.z += a1.z + a2.z + a3.z;
    a0.w += a1.w + a2.w + a3.w;
    g_aggX[(size_t)node * (DIM / 4) + lane] = a0;
}

// ---------------- final kernel (unchanged from round 10) ---------------------
// out[n] = relu( (1+eps)X[n].lin_W^T + aggX[n].C^T + deg[n]*c2 + lin_b )
__global__ void __launch_bounds__(512, 1)
final_kernel(const float* __restrict__ X,
             const float* __restrict__ lin_b,
             const float* __restrict__ eps_ptr, float* __restrict__ out) {
    extern __shared__ char smem[];
    const uint32_t sb = smem_u32(smem);
    const int tid = threadIdx.x;
    const int w = tid >> 5, t = tid & 31;
    const int s = w >> 1, h = w & 1;
    const int g = t >> 2, tig = t & 3;
    const int base = blockIdx.x * TILE_M;
    const float epsv = 1.0f + __ldg(eps_ptr);

    {
        const int row = tid >> 2;
        const int c0 = (tid & 3) * 32;
        const int grow = base + row;
        const bool v = (grow < N_NODES);
        const float4* xr = (const float4*)(X + (size_t)grow * DIM + c0);
        const float4* ar = (const float4*)((const float*)g_aggX + (size_t)grow * DIM + c0);
        #pragma unroll
        for (int c = 0; c < 32; c += 4) {
            float4 xv = v ? __ldg(xr + c / 4) : make_float4(0.f, 0.f, 0.f, 0.f);
            float4 av = v ? __ldg(ar + c / 4) : make_float4(0.f, 0.f, 0.f, 0.f);
            store_pair(smem + SM_A1H, smem + SM_A1L, row, c0 + c,
                       epsv * xv.x, epsv * xv.y);
            store_pair(smem + SM_A1H, smem + SM_A1L, row, c0 + c + 2,
                       epsv * xv.z, epsv * xv.w);
            store_pair(smem + SM_A2H, smem + SM_A2L, row, c0 + c, av.x, av.y);
            store_pair(smem + SM_A2H, smem + SM_A2L, row, c0 + c + 2, av.z, av.w);
        }
        const uint4* b1s = (const uint4*)(&g_Wh[0][(size_t)row * DIM + c0]);
        const uint4* b2s = (const uint4*)(&g_Wh[1][(size_t)row * DIM + c0]);
        uint4* b1d = (uint4*)(smem + SM_B1 + (uint32_t)row * ASTRIDE + (uint32_t)c0 * 2);
        uint4* b2d = (uint4*)(smem + SM_B2 + (uint32_t)row * ASTRIDE + (uint32_t)c0 * 2);
        #pragma unroll
        for (int i = 0; i < 4; i++) { b1d[i] = __ldg(b1s + i); b2d[i] = __ldg(b2s + i); }
    }
    __syncthreads();

    float acc[8][4];
    #pragma unroll
    for (int j = 0; j < 8; j++)
        #pragma unroll
        for (int i = 0; i < 4; i++) acc[j][i] = 0.f;

    #pragma unroll 1
    for (int k = 0; k < 8; k++) {
        const uint32_t a_off = (uint32_t)(s * 16 + (t & 15)) * ASTRIDE
                             + (uint32_t)k * 32 + (uint32_t)(t >> 4) * 16;
        uint32_t a1h[4], a1l[4], a2h[4], a2l[4];
        LDSM_X4(a1h, sb + SM_A1H + a_off);
        LDSM_X4(a1l, sb + SM_A1L + a_off);
        LDSM_X4(a2h, sb + SM_A2H + a_off);
        LDSM_X4(a2l, sb + SM_A2L + a_off);
        #pragma unroll
        for (int jp = 0; jp < 4; jp++) {
            const uint32_t b_off =
                  (uint32_t)((h * 8 + jp * 2) * 8 + (t >> 4) * 8 + (t & 7)) * ASTRIDE
                + (uint32_t)k * 32 + (uint32_t)((t >> 3) & 1) * 16;
            uint32_t b1[4], b2[4];
            LDSM_X4(b1, sb + SM_B1 + b_off);
            LDSM_X4(b2, sb + SM_B2 + b_off);
            MMA_FP16(acc[jp * 2 + 0], a1h, b1[0], b1[1]);
            MMA_FP16(acc[jp * 2 + 0], a1l, b1[0], b1[1]);
            MMA_FP16(acc[jp * 2 + 0], a2h, b2[0], b2[1]);
            MMA_FP16(acc[jp * 2 + 0], a2l, b2[0], b2[1]);
            MMA_FP16(acc[jp * 2 + 1], a1h, b1[2], b1[3]);
            MMA_FP16(acc[jp * 2 + 1], a1l, b1[2], b1[3]);
            MMA_FP16(acc[jp * 2 + 1], a2h, b2[2], b2[3]);
            MMA_FP16(acc[jp * 2 + 1], a2l, b2[2], b2[3]);
        }
    }

    const int r0 = s * 16 + g, r1 = r0 + 8;
    const int gr0 = base + r0, gr1 = base + r1;
    const bool v0 = (gr0 < N_NODES), v1 = (gr1 < N_NODES);
    const float d0 = v0 ? __ldg(&g_deg[gr0]) : 0.f;
    const float d1 = v1 ? __ldg(&g_deg[gr1]) : 0.f;
    #pragma unroll
    for (int j = 0; j < 8; j++) {
        const int col = h * 64 + j * 8 + 2 * tig;
        float2 lb = __ldg((const float2*)(lin_b + col));
        float2 c2 = __ldg((const float2*)(g_c2 + col));
        if (v0) {
            float2 o;
            o.x = fmaxf(acc[j][0] + d0 * c2.x + lb.x, 0.f);
            o.y = fmaxf(acc[j][1] + d0 * c2.y + lb.y, 0.f);
            *(float2*)(out + (size_t)gr0 * DIM + col) = o;
        }
        if (v1) {
            float2 o;
            o.x = fmaxf(acc[j][2] + d1 * c2.x + lb.x, 0.f);
            o.y = fmaxf(acc[j][3] + d1 * c2.y + lb.y, 0.f);
            *(float2*)(out + (size_t)gr1 * DIM + col) = o;
        }
    }
}

// ---------------- launch ----------------------------------------------------
extern "C" void kernel_launch(void* const* d_in, const int* in_sizes, int n_in,
                              void* d_out, int out_size) {
    const float* X   = nullptr;
    const void*  ei  = nullptr;
    const float* eps = nullptr;
    const float* w[2] = {nullptr, nullptr};   // [msg_w, lin_w]
    const float* b[2] = {nullptr, nullptr};   // [msg_b, lin_b]
    int wi = 0, bi = 0;
    for (int i = 0; i < n_in; i++) {
        const int s = in_sizes[i];
        if      (s == N_NODES * DIM) X   = (const float*)d_in[i];
        else if (s == 2 * N_EDGES)   ei  = d_in[i];
        else if (s == 1)             eps = (const float*)d_in[i];
        else if (s == DIM * DIM)   { if (wi < 2) w[wi++] = (const float*)d_in[i]; }
        else if (s == DIM)         { if (bi < 2) b[bi++] = (const float*)d_in[i]; }
    }
    float* out = (float*)d_out;

    cudaFuncSetAttribute(final_kernel, cudaFuncAttributeMaxDynamicSharedMemorySize, SM_TOTAL);

    const int edge_blocks = (N_EDGES + 255) / 256;   // 2442
    const int node_blocks = (N_NODES + 255) / 256;   // 196
    const int spmm_blocks = (N_NODES + 7) / 8;       // 6250 (warp/node)

    detect_ei_kernel<<<1, 256>>>((const unsigned*)ei);
    prep_w_kernel<<<(DIM * DIM + 255) / 256, 256>>>(w[1]);
    prep_c_kernel<<<DIM, DIM>>>(w[1], w[0], b[0]);
    zero_cnt_kernel<<<node_blocks, 256>>>();
    hist_kernel<<<edge_blocks, 256>>>(ei);
    scanA_kernel<<<NBLK, SCAN_BS>>>();
    scanB_kernel<<<1, 32>>>();
    scanC_kernel<<<node_blocks, 256>>>();
    reorder_kernel<<<edge_blocks, 256>>>(ei);
    spmm_kernel<<<spmm_blocks, 256>>>(X);
    final_kernel<<<NTILES, 512, SM_TOTAL>>>(X, b[1], eps, out);
}